// round 1
// baseline (speedup 1.0000x reference)
#include <cuda_runtime.h>

#define BB 2
#define NCH 7
#define VV 2097152          // 32*256*256
#define NI 16
#define NSG 17
#define NBINS 16384
#define SLOTS 8

// accumulator layout (floats)
#define OFF_CNT   0          // BB*NSG
#define OFF_SSUM  34         // BB*NSG*3
#define OFF_SSQ   136
#define OFF_XYZ   238
#define OFF_CCNT  340
#define OFF_CXYZ  374
#define OFF_VAR   476        // BB
#define OFF_SBG   478
#define OFF_SFG   480
#define OFF_ILOSS 482
#define OFF_S     484        // BB*NI*3
#define OFF_CEN   580        // BB*NI*3
#define ACC_N     676

__device__ float g_acc[ACC_N];
__device__ unsigned long long g_hist[(size_t)BB * NI * NBINS * SLOTS];

// ---------------------------------------------------------------- zero
__global__ void k_zero() {
    size_t total = (size_t)BB * NI * NBINS * SLOTS;
    for (size_t i = blockIdx.x * (size_t)blockDim.x + threadIdx.x; i < total;
         i += (size_t)gridDim.x * blockDim.x)
        g_hist[i] = 0ull;
    if (blockIdx.x == 0)
        for (int j = threadIdx.x; j < ACC_N; j += blockDim.x) g_acc[j] = 0.0f;
}

// ---------------------------------------------------------------- stats
// segmented sums per (batch, instance id 0..16):
// count, sum sig[3], sum sig^2[3], sum xyz[3], center count, center xyz sum[3]
__global__ void k_stats(const float* __restrict__ pred,
                        const int* __restrict__ inst,
                        const int* __restrict__ cent) {
    int b = blockIdx.y;
    __shared__ float sm[NSG * 14];
    for (int j = threadIdx.x; j < NSG * 14; j += blockDim.x) sm[j] = 0.0f;
    __syncthreads();

    const float* sig = pred + ((size_t)b * NCH + 3) * VV;
    const int* ib = inst + (size_t)b * VV;
    const int* cb = cent + (size_t)b * VV;

    for (int v = blockIdx.x * blockDim.x + threadIdx.x; v < VV;
         v += gridDim.x * blockDim.x) {
        int id = ib[v];
        float s0 = sig[v], s1 = sig[VV + v], s2 = sig[2 * VV + v];
        float x = (float)(v & 255) * (1.0f / 1023.0f);
        float y = (float)((v >> 8) & 255) * (1.0f / 1023.0f);
        float z = (float)(v >> 16) * (1.0f / 31.0f);
        float* base = sm + id * 14;
        atomicAdd(base + 0, 1.0f);
        atomicAdd(base + 1, s0);
        atomicAdd(base + 2, s1);
        atomicAdd(base + 3, s2);
        atomicAdd(base + 4, s0 * s0);
        atomicAdd(base + 5, s1 * s1);
        atomicAdd(base + 6, s2 * s2);
        atomicAdd(base + 7, x);
        atomicAdd(base + 8, y);
        atomicAdd(base + 9, z);
        if (cb[v] != 0) {  // robust: nonzero bits in either int32 or float32 encoding
            atomicAdd(base + 10, 1.0f);
            atomicAdd(base + 11, x);
            atomicAdd(base + 12, y);
            atomicAdd(base + 13, z);
        }
    }
    __syncthreads();
    for (int j = threadIdx.x; j < NSG * 14; j += blockDim.x) {
        int id = j / 14, f = j % 14;
        float vsm = sm[j];
        if (vsm != 0.0f) {
            float* dst;
            int bi = b * NSG + id;
            if (f == 0)       dst = &g_acc[OFF_CNT  + bi];
            else if (f < 4)   dst = &g_acc[OFF_SSUM + bi * 3 + (f - 1)];
            else if (f < 7)   dst = &g_acc[OFF_SSQ  + bi * 3 + (f - 4)];
            else if (f < 10)  dst = &g_acc[OFF_XYZ  + bi * 3 + (f - 7)];
            else if (f == 10) dst = &g_acc[OFF_CCNT + bi];
            else              dst = &g_acc[OFF_CXYZ + bi * 3 + (f - 11)];
            atomicAdd(dst, vsm);
        }
    }
}

// ---------------------------------------------------------------- params
__global__ void k_params() {
    int t = threadIdx.x;
    if (t >= BB * NSG) return;
    int b = t / NSG, id = t % NSG;
    float cnt = g_acc[OFF_CNT + t];
    float safe = fmaxf(cnt, 1.0f);
    float varsum = 0.0f;
    float m[3];
#pragma unroll
    for (int c = 0; c < 3; c++) {
        float ss = g_acc[OFF_SSUM + t * 3 + c];
        float sq = g_acc[OFF_SSQ + t * 3 + c];
        float mm = ss / safe;
        m[c] = mm;
        varsum += (sq - 2.0f * mm * ss + cnt * mm * mm) / safe;
    }
    if (id >= 1) {
        atomicAdd(&g_acc[OFF_VAR + b], varsum * (1.0f / (3.0f * NI)));
        float ccnt = g_acc[OFF_CCNT + t];
        bool one = (ccnt == 1.0f);
        int p = (b * NI + (id - 1)) * 3;
#pragma unroll
        for (int c = 0; c < 3; c++) {
            float cen = one ? g_acc[OFF_CXYZ + t * 3 + c]
                            : g_acc[OFF_XYZ + t * 3 + c] / safe;
            g_acc[OFF_CEN + p + c] = cen;
            g_acc[OFF_S + p + c] = expf(10.0f * m[c]);
        }
    }
}

// ---------------------------------------------------------------- dist + histogram + seed loss
// grid: (gx, BB, 2).  blockIdx.z selects 8 of 16 instances (register-resident params)
__global__ void __launch_bounds__(256) k_dist(const float* __restrict__ pred,
                                              const int* __restrict__ inst,
                                              const int* __restrict__ lab) {
    int b = blockIdx.y;
    int half = blockIdx.z;

    float c0[8], c1[8], c2[8], s0[8], s1[8], s2[8];
#pragma unroll
    for (int j = 0; j < 8; j++) {
        int p = (b * NI + half * 8 + j) * 3;
        s0[j] = g_acc[OFF_S + p];
        s1[j] = g_acc[OFF_S + p + 1];
        s2[j] = g_acc[OFF_S + p + 2];
        c0[j] = g_acc[OFF_CEN + p];
        c1[j] = g_acc[OFF_CEN + p + 1];
        c2[j] = g_acc[OFF_CEN + p + 2];
    }

    const float* pb = pred + (size_t)b * NCH * VV;
    const int* ib = inst + (size_t)b * VV;
    const int* lb = lab + (size_t)b * VV;
    unsigned long long* hb = g_hist + (size_t)b * NI * NBINS * SLOTS;
    int slot = threadIdx.x & (SLOTS - 1);

    float accbg = 0.0f, accfg = 0.0f;

    for (int v = blockIdx.x * blockDim.x + threadIdx.x; v < VV;
         v += gridDim.x * blockDim.x) {
        float x = (float)(v & 255) * (1.0f / 1023.0f);
        float y = (float)((v >> 8) & 255) * (1.0f / 1023.0f);
        float z = (float)(v >> 16) * (1.0f / 31.0f);
        float e0 = tanhf(pb[v]) + x;
        float e1 = tanhf(pb[VV + v]) + y;
        float e2 = tanhf(pb[2 * VV + v]) + z;
        int id = ib[v];
        float down = 0.0f;
#pragma unroll
        for (int j = 0; j < 8; j++) {
            int n = half * 8 + j;
            float dx = e0 - c0[j], dy = e1 - c1[j], dz = e2 - c2[j];
            float arg = s0[j] * dx * dx + s1[j] * dy * dy + s2[j] * dz * dz;
            float d = __expf(-arg);
            bool fg = (id == n + 1);
            if (fg) down = d;
            float e = fg ? fmaf(-2.0f, d, 2.0f) : 2.0f * d;
            int bin = (int)(e * (NBINS * 0.5f));
            if (bin > NBINS - 1) bin = NBINS - 1;
            atomicAdd(&hb[((size_t)n * NBINS + bin) * SLOTS + slot],
                      fg ? (1ull << 32) : 1ull);
        }
        float sd = 1.0f / (1.0f + __expf(-pb[6 * VV + v]));
        if (id > half * 8 && id <= half * 8 + 8) {
            float t = sd - down;
            accfg += t * t;
        }
        if (half == 0 && lb[v] == 0) accbg += sd * sd;
    }

    __shared__ float r1[256], r2[256];
    int t = threadIdx.x;
    r1[t] = accbg;
    r2[t] = accfg;
    __syncthreads();
    for (int s = 128; s > 0; s >>= 1) {
        if (t < s) { r1[t] += r1[t + s]; r2[t] += r2[t + s]; }
        __syncthreads();
    }
    if (t == 0) {
        if (half == 0) atomicAdd(&g_acc[OFF_SBG + b], r1[0]);
        atomicAdd(&g_acc[OFF_SFG + b], r2[0]);
    }
}

// ---------------------------------------------------------------- lovasz from histogram
__global__ void k_lovasz() {
    int bn = blockIdx.x;       // b*16 + n
    int b = bn >> 4;
    const unsigned long long* H = g_hist + (size_t)bn * NBINS * SLOTS;
    __shared__ float sF[257], sB[257];
    __shared__ float sred[256];
    __shared__ int sMinR;
    int t = threadIdx.x;
    if (t == 0) sMinR = NBINS;
    const int CH = NBINS / 256;  // 64 bins per thread, descending-error order

    float locF = 0.0f, locB = 0.0f;
    for (int i = 0; i < CH; i++) {
        int bin = NBINS - 1 - (t * CH + i);
        unsigned long long s = 0;
#pragma unroll
        for (int sl = 0; sl < SLOTS; sl++) s += H[(size_t)bin * SLOTS + sl];
        locF += (float)(unsigned)(s >> 32);
        locB += (float)(unsigned)(s & 0xffffffffu);
    }
    sF[t] = locF;
    sB[t] = locB;
    __syncthreads();
    if (t == 0) {
        float pf = 0.0f, pq = 0.0f;
        for (int i = 0; i < 256; i++) {
            float f = sF[i], bb = sB[i];
            sF[i] = pf; sB[i] = pq;
            pf += f; pq += bb;
        }
        sF[256] = pf; sB[256] = pq;
    }
    __syncthreads();
    float G = sF[256];
    float contrib = 0.0f;
    if (G > 0.0f) {
        float P = sF[t], Q = sB[t];
        for (int i = 0; i < CH; i++) {
            int bin = NBINS - 1 - (t * CH + i);
            unsigned long long s = 0;
#pragma unroll
            for (int sl = 0; sl < SLOTS; sl++) s += H[(size_t)bin * SLOTS + sl];
            float f = (float)(unsigned)(s >> 32);
            float bb = (float)(unsigned)(s & 0xffffffffu);
            if (f > 0.0f || bb > 0.0f) {
                float e = ((float)bin + 0.5f) * (2.0f / NBINS);
                float gq = G + Q;
                float num = (G - P) * bb + f * gq;   // cancellation-free jacc delta
                float den = gq * (gq + bb);
                contrib += e * num / den;
                P += f;
                Q += bb;
            }
        }
    } else {  // degenerate: no fg voxels -> loss = max error
        for (int i = 0; i < CH; i++) {
            int r = t * CH + i;
            int bin = NBINS - 1 - r;
            unsigned long long s = 0;
            for (int sl = 0; sl < SLOTS; sl++) s += H[(size_t)bin * SLOTS + sl];
            if (s) { atomicMin(&sMinR, r); break; }
        }
    }
    sred[t] = contrib;
    __syncthreads();
    for (int s2 = 128; s2 > 0; s2 >>= 1) {
        if (t < s2) sred[t] += sred[t + s2];
        __syncthreads();
    }
    if (t == 0) {
        float total = sred[0];
        if (G <= 0.0f && sMinR < NBINS)
            total = ((float)(NBINS - 1 - sMinR) + 0.5f) * (2.0f / NBINS);
        atomicAdd(&g_acc[OFF_ILOSS + b], total);
    }
}

// ---------------------------------------------------------------- final combine
__global__ void k_final(float* out) {
    if (threadIdx.x == 0 && blockIdx.x == 0) {
        float r = 0.0f;
        for (int b = 0; b < BB; b++) {
            float il = g_acc[OFF_ILOSS + b] * (1.0f / NI);        // instance loss (W=1)
            float vl = g_acc[OFF_VAR + b];                        // var loss
            float sl = (g_acc[OFF_SBG + b] + 10.0f * g_acc[OFF_SFG + b]) * (1.0f / VV);
            r += il + 10.0f * vl + sl;
        }
        out[0] = r * (1.0f / BB);
    }
}

// ---------------------------------------------------------------- launch
extern "C" void kernel_launch(void* const* d_in, const int* in_sizes, int n_in,
                              void* d_out, int out_size) {
    const float* pred = (const float*)d_in[0];
    const int* inst = (const int*)d_in[1];
    const int* lab = (const int*)d_in[2];
    const int* cent = (const int*)d_in[3];

    k_zero<<<1024, 256>>>();
    {
        dim3 g(512, BB);
        k_stats<<<g, 256>>>(pred, inst, cent);
    }
    k_params<<<1, 64>>>();
    {
        dim3 g(1024, BB, 2);
        k_dist<<<g, 256>>>(pred, inst, lab);
    }
    k_lovasz<<<BB * NI, 256>>>();
    k_final<<<1, 1>>>((float*)d_out);
}